// round 1
// baseline (speedup 1.0000x reference)
#include <cuda_runtime.h>
#include <math.h>

// EarthAttention3D (Pangu-Weather windowed attention), fixed shapes:
//   B_=960 windows, L=144, C=192, HEADS=6, hd=32, W_WINS=15, NW=64
#define BWIN 960
#define LTOK 144
#define CDIM 192
#define NH   6
#define HDM  32
#define WWINS 15
#define TABNW 64

// Scratch (static device globals; no runtime allocation allowed)
__device__ float g_qkv[(size_t)BWIN * LTOK * 3 * CDIM];  // (960,144,576)
__device__ float g_att[(size_t)BWIN * LTOK * CDIM];      // (960,144,192) in (l, head*32+d) layout

// ---------------------------------------------------------------------------
// Generic fp32 GEMM:  C[M,N] = A[M,K] @ B[K,N] + bias[N]
// Tiles: 64x64 block, BK=32, 256 threads, 4x4 micro-tile per thread.
// Requires 64|M, 64|N, 32|K (true for all three uses here).
// ---------------------------------------------------------------------------
__global__ void __launch_bounds__(256) gemm_bias_kernel(
    const float* __restrict__ A, const float* __restrict__ B,
    const float* __restrict__ bias, float* __restrict__ C,
    int M, int N, int K)
{
    __shared__ float As[64][36];   // [row][kk], padded to 36 for aligned float4 + fewer conflicts
    __shared__ float Bs[32][64];   // [kk][col]

    const int tid = threadIdx.x;
    const int tx = tid & 15;       // 16 cols of threads
    const int ty = tid >> 4;       // 16 rows of threads
    const int row0 = blockIdx.y << 6;
    const int col0 = blockIdx.x << 6;

    float acc[4][4];
#pragma unroll
    for (int i = 0; i < 4; ++i)
#pragma unroll
        for (int j = 0; j < 4; ++j) acc[i][j] = 0.f;

    for (int kt = 0; kt < K; kt += 32) {
        // Load A tile: 64x32 floats, float4 per thread x2
#pragma unroll
        for (int i = tid * 4; i < 64 * 32; i += 1024) {
            int r  = i >> 5;
            int kk = i & 31;
            *(float4*)&As[r][kk] =
                *(const float4*)&A[(size_t)(row0 + r) * K + kt + kk];
        }
        // Load B tile: 32x64
#pragma unroll
        for (int i = tid * 4; i < 32 * 64; i += 1024) {
            int kk = i >> 6;
            int c  = i & 63;
            *(float4*)&Bs[kk][c] =
                *(const float4*)&B[(size_t)(kt + kk) * N + col0 + c];
        }
        __syncthreads();

#pragma unroll
        for (int kk = 0; kk < 32; ++kk) {
            float4 b4 = *(const float4*)&Bs[kk][tx * 4];
            float a0 = As[ty * 4 + 0][kk];
            float a1 = As[ty * 4 + 1][kk];
            float a2 = As[ty * 4 + 2][kk];
            float a3 = As[ty * 4 + 3][kk];
            acc[0][0] += a0 * b4.x; acc[0][1] += a0 * b4.y; acc[0][2] += a0 * b4.z; acc[0][3] += a0 * b4.w;
            acc[1][0] += a1 * b4.x; acc[1][1] += a1 * b4.y; acc[1][2] += a1 * b4.z; acc[1][3] += a1 * b4.w;
            acc[2][0] += a2 * b4.x; acc[2][1] += a2 * b4.y; acc[2][2] += a2 * b4.z; acc[2][3] += a2 * b4.w;
            acc[3][0] += a3 * b4.x; acc[3][1] += a3 * b4.y; acc[3][2] += a3 * b4.z; acc[3][3] += a3 * b4.w;
        }
        __syncthreads();
    }

    float4 bv = *(const float4*)&bias[col0 + tx * 4];
#pragma unroll
    for (int i = 0; i < 4; ++i) {
        float4 o;
        o.x = acc[i][0] + bv.x;
        o.y = acc[i][1] + bv.y;
        o.z = acc[i][2] + bv.z;
        o.w = acc[i][3] + bv.w;
        *(float4*)&C[(size_t)(row0 + ty * 4 + i) * N + col0 + tx * 4] = o;
    }
}

// ---------------------------------------------------------------------------
// Fused attention per (window, head):
//   S = scale*Q @ K^T + bias_table[pos_idx][g][head] + mask[wi]
//   P = softmax(S); out = P @ V   -> g_att (wi, l, head*32+d)
// Block: 256 threads = 8 warps; each warp owns 18 rows, processed in 3 passes
// of 6 rows (register-blocked so each K/V smem read feeds 6 FMAs).
// ---------------------------------------------------------------------------
#define QKV_PITCH 36   // padded floats per Q/K/V smem row

__global__ void __launch_bounds__(256, 2) attn_kernel(
    const float* __restrict__ qkv, const float* __restrict__ mask,
    const float* __restrict__ bias_table, const int* __restrict__ pos,
    float* __restrict__ att)
{
    const int head = blockIdx.x;      // 0..5
    const int wi   = blockIdx.y;      // 0..959
    const int grp  = wi / WWINS;      // bias-sharing group 0..63
    const int tid  = threadIdx.x;
    const int w    = tid >> 5;
    const int lane = tid & 31;

    extern __shared__ float sm[];
    float* Qs = sm;                         // 144*36
    float* Ks = Qs + LTOK * QKV_PITCH;      // 144*36
    float* Vs = Ks + LTOK * QKV_PITCH;      // 144*36
    float* Pb = Vs + LTOK * QKV_PITCH;      // 8 warps * 6 rows * 144

    const float scale = 0.17677669529663687f;  // 32^-0.5
    const float* qbase = qkv + (size_t)wi * LTOK * (3 * CDIM) + head * HDM;

    for (int i = tid; i < LTOK * HDM; i += 256) {
        int l = i >> 5;
        int d = i & 31;
        const float* p = qbase + (size_t)l * (3 * CDIM);
        Qs[l * QKV_PITCH + d] = p[d] * scale;
        Ks[l * QKV_PITCH + d] = p[CDIM + d];
        Vs[l * QKV_PITCH + d] = p[2 * CDIM + d];
    }
    __syncthreads();

    const float* mrow = mask + (size_t)wi * LTOK * LTOK;
    float* prow = Pb + w * 6 * LTOK;
    const int l0 = w * 18;

    for (int pass = 0; pass < 3; ++pass) {
        const int lbase = l0 + pass * 6;

        // ---- S = scale*Q @ K^T (6 rows x 5 m-slots per lane) ----
        float acc[6][5];
#pragma unroll
        for (int r = 0; r < 6; ++r)
#pragma unroll
            for (int j = 0; j < 5; ++j) acc[r][j] = 0.f;

#pragma unroll
        for (int dc = 0; dc < 8; ++dc) {
            float4 kv[5];
#pragma unroll
            for (int j = 0; j < 5; ++j) {
                int m = lane + 32 * j;
                kv[j] = (m < LTOK)
                    ? *(const float4*)&Ks[m * QKV_PITCH + dc * 4]
                    : make_float4(0.f, 0.f, 0.f, 0.f);
            }
#pragma unroll
            for (int r = 0; r < 6; ++r) {
                float4 qv = *(const float4*)&Qs[(lbase + r) * QKV_PITCH + dc * 4];
#pragma unroll
                for (int j = 0; j < 5; ++j) {
                    acc[r][j] += qv.x * kv[j].x + qv.y * kv[j].y
                               + qv.z * kv[j].z + qv.w * kv[j].w;
                }
            }
        }

        // ---- bias + mask + softmax per row, write P to warp buffer ----
#pragma unroll
        for (int r = 0; r < 6; ++r) {
            const int l = lbase + r;
            float s[5];
#pragma unroll
            for (int j = 0; j < 5; ++j) {
                int m = lane + 32 * j;
                if (m < LTOK) {
                    int pi = pos[l * LTOK + m];
                    s[j] = acc[r][j]
                         + bias_table[(size_t)pi * (TABNW * NH) + grp * NH + head]
                         + mrow[l * LTOK + m];
                } else {
                    s[j] = -1e30f;
                }
            }
            float mx = s[0];
#pragma unroll
            for (int j = 1; j < 5; ++j) mx = fmaxf(mx, s[j]);
#pragma unroll
            for (int o = 16; o; o >>= 1)
                mx = fmaxf(mx, __shfl_xor_sync(0xffffffffu, mx, o));

            float sum = 0.f;
#pragma unroll
            for (int j = 0; j < 5; ++j) {
                float e = __expf(s[j] - mx);   // s[j]=-1e30 underflows to 0
                s[j] = e;
                sum += e;
            }
#pragma unroll
            for (int o = 16; o; o >>= 1)
                sum += __shfl_xor_sync(0xffffffffu, sum, o);
            float inv = 1.0f / sum;
#pragma unroll
            for (int j = 0; j < 5; ++j) {
                int m = lane + 32 * j;
                if (m < LTOK) prow[r * LTOK + m] = s[j] * inv;
            }
        }
        __syncwarp();

        // ---- out = P @ V ; lane = output dim d ----
        float oacc[6] = {0.f, 0.f, 0.f, 0.f, 0.f, 0.f};
        for (int m = 0; m < LTOK; m += 4) {
            float v0 = Vs[(m + 0) * QKV_PITCH + lane];
            float v1 = Vs[(m + 1) * QKV_PITCH + lane];
            float v2 = Vs[(m + 2) * QKV_PITCH + lane];
            float v3 = Vs[(m + 3) * QKV_PITCH + lane];
#pragma unroll
            for (int r = 0; r < 6; ++r) {
                float4 p = *(const float4*)&prow[r * LTOK + m];
                oacc[r] += p.x * v0 + p.y * v1 + p.z * v2 + p.w * v3;
            }
        }
        float* obase = att + (size_t)wi * LTOK * CDIM + head * HDM + lane;
#pragma unroll
        for (int r = 0; r < 6; ++r)
            obase[(size_t)(lbase + r) * CDIM] = oacc[r];
        __syncwarp();   // prow reused next pass
    }
}

// ---------------------------------------------------------------------------
extern "C" void kernel_launch(void* const* d_in, const int* in_sizes, int n_in,
                              void* d_out, int out_size)
{
    const float* x          = (const float*)d_in[0];  // (960,144,192)
    const float* mask       = (const float*)d_in[1];  // (960,144,144)
    const float* W1         = (const float*)d_in[2];  // (192,576)
    const float* b1         = (const float*)d_in[3];  // (576,)
    const float* W2         = (const float*)d_in[4];  // (192,192)
    const float* b2         = (const float*)d_in[5];  // (192,)
    const float* bias_table = (const float*)d_in[6];  // (3312,64,6)
    const int*   pos        = (const int*)d_in[7];    // (144,144)
    float* out = (float*)d_out;

    void* qkv_p = nullptr;
    void* att_p = nullptr;
    cudaGetSymbolAddress(&qkv_p, g_qkv);
    cudaGetSymbolAddress(&att_p, g_att);
    float* qkv = (float*)qkv_p;
    float* att = (float*)att_p;

    const int M = BWIN * LTOK;  // 138240

    // Opt-in to >48KB dynamic smem for the attention kernel (every call; cheap).
    const int attn_smem = (3 * LTOK * QKV_PITCH + 8 * 6 * LTOK) * (int)sizeof(float); // 89856
    cudaFuncSetAttribute(attn_kernel, cudaFuncAttributeMaxDynamicSharedMemorySize, attn_smem);

    // 1) QKV projection: (138240,192) @ (192,576) + b1
    {
        dim3 grid(3 * CDIM / 64, M / 64);  // (9, 2160)
        gemm_bias_kernel<<<grid, 256>>>(x, W1, b1, qkv, M, 3 * CDIM, CDIM);
    }
    // 2) Fused windowed attention
    {
        dim3 grid(NH, BWIN);               // (6, 960)
        attn_kernel<<<grid, 256, attn_smem>>>(qkv, mask, bias_table, pos, att);
    }
    // 3) Output projection: (138240,192) @ (192,192) + b2
    {
        dim3 grid(CDIM / 64, M / 64);      // (3, 2160)
        gemm_bias_kernel<<<grid, 256>>>(att, W2, b2, out, M, CDIM, CDIM);
    }
}